// round 7
// baseline (speedup 1.0000x reference)
#include <cuda_runtime.h>
#include <cstdint>

#define NN 50000
#define DD 64
#define EE 800000
#define SCAN_BS 1024
#define NBLK ((NN + SCAN_BS - 1) / SCAN_BS)   // 49

// Scratch (no cudaMalloc allowed)
__device__ float g_AGG[NN * DD];     // reused for both aggregation passes
__device__ float g_H[NN * DD];
__device__ int   g_counts[NN];
__device__ int   g_offsets[NN];
__device__ int   g_cursor[NN];
__device__ int   g_bsum[NBLK + 1];
__device__ int2  g_recs[EE];         // (src, bitcast(weight)) binned by dst

// ---------------------------------------------------------------------------
// edge_index dtype is ambiguous (jnp.int64 without x64 -> int32); detect at
// runtime: int64 values < 50000 have all-zero odd 32-bit words.
// ---------------------------------------------------------------------------
__device__ __forceinline__ bool detect_i64(const int* __restrict__ ei32) {
    return (ei32[1] | ei32[3] | ei32[5] | ei32[7] |
            ei32[9] | ei32[11] | ei32[13] | ei32[15]) == 0;
}
__device__ __forceinline__ void load_edge(const int* __restrict__ ei32, bool is64,
                                          int e, int& src, int& dst) {
    if (is64) {
        const long long* ei64 = (const long long*)ei32;
        src = (int)ei64[e];
        dst = (int)ei64[EE + e];
    } else {
        src = ei32[e];
        dst = ei32[EE + e];
    }
}

// f32x2 packed helpers (FFMA2 is only reachable via PTX fma.rn.f32x2)
__device__ __forceinline__ unsigned long long pk2(float lo, float hi) {
    unsigned long long r;
    asm("mov.b64 %0, {%1, %2};" : "=l"(r) : "f"(lo), "f"(hi));
    return r;
}
__device__ __forceinline__ void upk2(unsigned long long v, float& lo, float& hi) {
    asm("mov.b64 {%0, %1}, %2;" : "=f"(lo), "=f"(hi) : "l"(v));
}
__device__ __forceinline__ void fma2(unsigned long long& d,
                                     unsigned long long a, unsigned long long b) {
    asm("fma.rn.f32x2 %0, %1, %2, %0;" : "+l"(d) : "l"(a), "l"(b));
}

// ---------------------------------------------------------------------------
__global__ __launch_bounds__(256) void zero_counts_kernel() {
    int i = blockIdx.x * blockDim.x + threadIdx.x;
    if (i < NN) g_counts[i] = 0;
}

__global__ __launch_bounds__(256) void hist_kernel(const int* __restrict__ ei32) {
    int e = blockIdx.x * blockDim.x + threadIdx.x;
    if (e >= EE) return;
    bool is64 = detect_i64(ei32);
    int dst = is64 ? ei32[2 * (EE + e)] : ei32[EE + e];
    atomicAdd(&g_counts[dst], 1);
}

// Block-wide inclusive scan (Hillis-Steele): block-exclusive offsets + block sums.
__global__ __launch_bounds__(SCAN_BS) void scan1_kernel() {
    __shared__ int s[SCAN_BS];
    int i = blockIdx.x * SCAN_BS + threadIdx.x;
    int v = (i < NN) ? g_counts[i] : 0;
    s[threadIdx.x] = v;
    __syncthreads();
#pragma unroll
    for (int off = 1; off < SCAN_BS; off <<= 1) {
        int y = (threadIdx.x >= off) ? s[threadIdx.x - off] : 0;
        __syncthreads();
        s[threadIdx.x] += y;
        __syncthreads();
    }
    if (i < NN) g_offsets[i] = s[threadIdx.x] - v;   // exclusive within block
    if (threadIdx.x == SCAN_BS - 1) g_bsum[blockIdx.x] = s[SCAN_BS - 1];
}

// Apply cross-block prefix. Each 256-thread block lies inside ONE scan block
// (256 | 1024), so sb = blockIdx>>2 is uniform: thread 0 sums <=48 block sums.
__global__ __launch_bounds__(256) void scan3_kernel() {
    __shared__ int prefix;
    if (threadIdx.x == 0) {
        int sb = blockIdx.x >> 2;
        int run = 0;
        for (int b = 0; b < sb; b++) run += g_bsum[b];
        prefix = run;
    }
    __syncthreads();
    int i = blockIdx.x * blockDim.x + threadIdx.x;
    if (i < NN) {
        int o = g_offsets[i] + prefix;
        g_offsets[i] = o;
        g_cursor[i]  = o;
    }
}

__global__ __launch_bounds__(256) void fill_kernel(const int* __restrict__ ei32,
                                                   const float* __restrict__ ew) {
    int e = blockIdx.x * blockDim.x + threadIdx.x;
    if (e >= EE) return;
    bool is64 = detect_i64(ei32);
    int src, dst;
    load_edge(ei32, is64, e, src, dst);
    int pos = atomicAdd(&g_cursor[dst], 1);
    g_recs[pos] = make_int2(src, __float_as_int(ew[e]));
}

// ---------------------------------------------------------------------------
// Gather: one warp per destination node, no atomics.
// Half-warps process edges pairwise, unrolled x2 (4 edges in flight per warp)
// to raise MLP against L2 latency; lane j<16 owns float4 j of the row.
// ---------------------------------------------------------------------------
__global__ __launch_bounds__(256) void gather_kernel(const float4* __restrict__ Xv,
                                                     float4* __restrict__ agg) {
    int warp = (blockIdx.x * blockDim.x + threadIdx.x) >> 5;
    if (warp >= NN) return;
    int lane = threadIdx.x & 31;
    int half = lane >> 4;
    int j    = lane & 15;

    int start = g_offsets[warp];
    int cnt   = g_counts[warp];

    float4 acc = make_float4(0.f, 0.f, 0.f, 0.f);
    int i = half;
    // 2-deep unroll: issue both rec+row loads before consuming either
    for (; i + 2 < cnt; i += 4) {
        int2  rec0 = g_recs[start + i];
        int2  rec1 = g_recs[start + i + 2];
        float4 x0  = Xv[rec0.x * 16 + j];
        float4 x1  = Xv[rec1.x * 16 + j];
        float w0   = __int_as_float(rec0.y);
        float w1   = __int_as_float(rec1.y);
        acc.x += x0.x * w0;  acc.y += x0.y * w0;
        acc.z += x0.z * w0;  acc.w += x0.w * w0;
        acc.x += x1.x * w1;  acc.y += x1.y * w1;
        acc.z += x1.z * w1;  acc.w += x1.w * w1;
    }
    if (i < cnt) {
        int2  rec = g_recs[start + i];
        float w   = __int_as_float(rec.y);
        float4 x  = Xv[rec.x * 16 + j];
        acc.x += x.x * w;  acc.y += x.y * w;
        acc.z += x.z * w;  acc.w += x.w * w;
    }
    acc.x += __shfl_down_sync(0xffffffffu, acc.x, 16);
    acc.y += __shfl_down_sync(0xffffffffu, acc.y, 16);
    acc.z += __shfl_down_sync(0xffffffffu, acc.z, 16);
    acc.w += __shfl_down_sync(0xffffffffu, acc.w, 16);
    if (half == 0) agg[warp * 16 + j] = acc;
}

// ---------------------------------------------------------------------------
// Fused dual-GEMM + bias + sigmoid, packed-FFMA2 version.
//   out = sigmoid(A @ Wrel^T + R @ Wroot^T + bias)
// 128 threads, 64-row tile. Thread (cg = tid&7, rg = tid>>3) computes
// 8 cols {cg*8 .. cg*8+7} (as 4 f32x2 column-pairs) x 4 rows {rg*4+t}.
// Weights pre-packed in smem as float2 (W[2q][k], W[2q+1][k]) at
// slot = k*32 + (q&3)*8 + (q>>2): the 8 lanes of a cg-group read 8 distinct
// banks (conflict-free LDS.64, broadcast across rg-groups).
// A/R rows read straight from gmem (8 same-address lanes coalesce).
// ---------------------------------------------------------------------------
__global__ __launch_bounds__(128) void gemm_bias_sigmoid_kernel(
    const float* __restrict__ A,
    const float* __restrict__ R,
    const float* __restrict__ Wrel,   // [64,64] row-major [out][in]
    const float* __restrict__ Wroot,
    const float* __restrict__ b0, const float* __restrict__ b1,
    const float* __restrict__ b2, const float* __restrict__ b3,
    float* __restrict__ out)
{
    __shared__ float2 W2r[64 * 32];   // 16KB packed column-pairs
    __shared__ float2 W2o[64 * 32];
    __shared__ float  Ws[64 * 64];    // 16KB staging (coalesced gmem load)

    int tid = threadIdx.x;

    // Stage + pack Wrel
    for (int i = tid; i < 1024; i += 128)
        ((float4*)Ws)[i] = ((const float4*)Wrel)[i];
    __syncthreads();
    for (int idx = tid; idx < 2048; idx += 128) {
        int k = idx >> 5, q = idx & 31;
        int slot = k * 32 + (q & 3) * 8 + (q >> 2);
        W2r[slot] = make_float2(Ws[(2 * q) * 64 + k], Ws[(2 * q + 1) * 64 + k]);
    }
    __syncthreads();
    // Stage + pack Wroot
    for (int i = tid; i < 1024; i += 128)
        ((float4*)Ws)[i] = ((const float4*)Wroot)[i];
    __syncthreads();
    for (int idx = tid; idx < 2048; idx += 128) {
        int k = idx >> 5, q = idx & 31;
        int slot = k * 32 + (q & 3) * 8 + (q >> 2);
        W2o[slot] = make_float2(Ws[(2 * q) * 64 + k], Ws[(2 * q + 1) * 64 + k]);
    }
    __syncthreads();

    int cg = tid & 7;
    int rg = tid >> 3;
    int row0 = blockIdx.x * 64 + rg * 4;

    // Init accumulators with bias (column pairs p -> cols cg*8+2p, cg*8+2p+1)
    unsigned long long acc[4][4];
#pragma unroll
    for (int p = 0; p < 4; p++) {
        int c0 = cg * 8 + 2 * p;
        float blo = b0[c0]     + b1[c0];
        float bhi = b0[c0 + 1] + b1[c0 + 1];
        if (b2 != nullptr) {
            blo += b2[c0]     + b3[c0];
            bhi += b2[c0 + 1] + b3[c0 + 1];
        }
        unsigned long long binit = pk2(blo, bhi);
#pragma unroll
        for (int t = 0; t < 4; t++) acc[p][t] = binit;
    }

    const float4* A4 = (const float4*)A;
    const float4* R4 = (const float4*)R;
    bool full = (row0 + 3 < NN);

    const unsigned long long* W2rQ = (const unsigned long long*)W2r;
    const unsigned long long* W2oQ = (const unsigned long long*)W2o;

#pragma unroll 2
    for (int kq = 0; kq < 16; kq++) {
        float4 a[4], r[4];
#pragma unroll
        for (int t = 0; t < 4; t++) {
            int row = row0 + t;
            if (full || row < NN) {
                a[t] = A4[row * 16 + kq];
                r[t] = R4[row * 16 + kq];
            } else {
                a[t] = make_float4(0.f, 0.f, 0.f, 0.f);
                r[t] = make_float4(0.f, 0.f, 0.f, 0.f);
            }
        }
#pragma unroll
        for (int comp = 0; comp < 4; comp++) {
            int k = kq * 4 + comp;
            unsigned long long a2[4], r2[4];
#pragma unroll
            for (int t = 0; t < 4; t++) {
                float av = (comp == 0) ? a[t].x : (comp == 1) ? a[t].y
                         : (comp == 2) ? a[t].z : a[t].w;
                float rv = (comp == 0) ? r[t].x : (comp == 1) ? r[t].y
                         : (comp == 2) ? r[t].z : r[t].w;
                a2[t] = pk2(av, av);
                r2[t] = pk2(rv, rv);
            }
#pragma unroll
            for (int p = 0; p < 4; p++) {
                unsigned long long wr2 = W2rQ[k * 32 + p * 8 + cg];
                unsigned long long wo2 = W2oQ[k * 32 + p * 8 + cg];
#pragma unroll
                for (int t = 0; t < 4; t++) {
                    fma2(acc[p][t], a2[t], wr2);
                    fma2(acc[p][t], r2[t], wo2);
                }
            }
        }
    }

#pragma unroll
    for (int t = 0; t < 4; t++) {
        int row = row0 + t;
        if (row < NN) {
            float v[8];
#pragma unroll
            for (int p = 0; p < 4; p++) upk2(acc[p][t], v[2 * p], v[2 * p + 1]);
            float4 o0, o1;
            o0.x = 1.f / (1.f + __expf(-v[0]));
            o0.y = 1.f / (1.f + __expf(-v[1]));
            o0.z = 1.f / (1.f + __expf(-v[2]));
            o0.w = 1.f / (1.f + __expf(-v[3]));
            o1.x = 1.f / (1.f + __expf(-v[4]));
            o1.y = 1.f / (1.f + __expf(-v[5]));
            o1.z = 1.f / (1.f + __expf(-v[6]));
            o1.w = 1.f / (1.f + __expf(-v[7]));
            float4* op = (float4*)&out[row * DD + cg * 8];
            op[0] = o0;
            op[1] = o1;
        }
    }
}

// ---------------------------------------------------------------------------
extern "C" void kernel_launch(void* const* d_in, const int* in_sizes, int n_in,
                              void* d_out, int out_size)
{
    const float* X      = (const float*)d_in[0];
    const int*   ei     = (const int*)  d_in[1];   // raw; dtype auto-detected
    const float* ew     = (const float*)d_in[2];
    const float* Wrel1  = (const float*)d_in[3];
    const float* brel1  = (const float*)d_in[4];
    const float* Wroot1 = (const float*)d_in[5];
    const float* broot1 = (const float*)d_in[6];
    const float* brel2  = (const float*)d_in[8];
    const float* broot2 = (const float*)d_in[10];
    const float* Wrel3  = (const float*)d_in[11];
    const float* brel3  = (const float*)d_in[12];
    const float* Wroot3 = (const float*)d_in[13];
    const float* broot3 = (const float*)d_in[14];
    float* out = (float*)d_out;

    float *agg, *h;
    cudaGetSymbolAddress((void**)&agg, g_AGG);
    cudaGetSymbolAddress((void**)&h,   g_H);

    // --- CSR build (once; shared by both aggregation passes) ---
    zero_counts_kernel<<<(NN + 255) / 256, 256>>>();
    hist_kernel<<<(EE + 255) / 256, 256>>>(ei);
    scan1_kernel<<<NBLK, SCAN_BS>>>();
    scan3_kernel<<<(NN + 255) / 256, 256>>>();
    fill_kernel<<<(EE + 255) / 256, 256>>>(ei, ew);

    // --- pass 1: AGG = scatter(X[src]*w -> dst), atomic-free gather ---
    gather_kernel<<<(NN * 32 + 255) / 256, 256>>>((const float4*)X, (float4*)agg);

    // H = sigmoid(AGG@Wrel1^T + X@Wroot1^T + brel1+broot1+brel2+broot2)
    gemm_bias_sigmoid_kernel<<<(NN + 63) / 64, 128>>>(
        agg, X, Wrel1, Wroot1, brel1, broot1, brel2, broot2, h);

    // --- pass 2: AGG = scatter(H[src]*w -> dst) ---
    gather_kernel<<<(NN * 32 + 255) / 256, 256>>>((const float4*)h, (float4*)agg);

    // out = sigmoid(AGG@Wrel3^T + H@Wroot3^T + brel3+broot3)
    gemm_bias_sigmoid_kernel<<<(NN + 63) / 64, 128>>>(
        agg, h, Wrel3, Wroot3, brel3, broot3, nullptr, nullptr, out);
}

// round 10
// speedup vs baseline: 1.2800x; 1.2800x over previous
#include <cuda_runtime.h>
#include <cstdint>

#define NN 50000
#define DD 64
#define EE 800000
#define SCAN_BS 1024
#define NBLK ((NN + SCAN_BS - 1) / SCAN_BS)   // 49

// Scratch (no cudaMalloc allowed)
__device__ float g_AGG[NN * DD];     // reused for both aggregation passes
__device__ float g_H[NN * DD];
__device__ int   g_counts[NN];
__device__ int   g_offsets[NN];
__device__ int   g_cursor[NN];
__device__ int   g_bsum[64];
__device__ int2  g_recs[EE];         // (src, bitcast(weight)) binned by dst

// ---------------------------------------------------------------------------
// edge_index dtype is ambiguous (jnp.int64 without x64 -> int32); detect at
// runtime: int64 values < 50000 have all-zero odd 32-bit words.
// ---------------------------------------------------------------------------
__device__ __forceinline__ bool detect_i64(const int* __restrict__ ei32) {
    return (ei32[1] | ei32[3] | ei32[5] | ei32[7] |
            ei32[9] | ei32[11] | ei32[13] | ei32[15]) == 0;
}
__device__ __forceinline__ void load_edge(const int* __restrict__ ei32, bool is64,
                                          int e, int& src, int& dst) {
    if (is64) {
        const long long* ei64 = (const long long*)ei32;
        src = (int)ei64[e];
        dst = (int)ei64[EE + e];
    } else {
        src = ei32[e];
        dst = ei32[EE + e];
    }
}

// ---------------------------------------------------------------------------
__global__ __launch_bounds__(256) void zero_counts_kernel() {
    int i = blockIdx.x * blockDim.x + threadIdx.x;
    if (i < NN) g_counts[i] = 0;
}

__global__ __launch_bounds__(256) void hist_kernel(const int* __restrict__ ei32) {
    int e = blockIdx.x * blockDim.x + threadIdx.x;
    if (e >= EE) return;
    bool is64 = detect_i64(ei32);
    int dst = is64 ? ei32[2 * (EE + e)] : ei32[EE + e];
    atomicAdd(&g_counts[dst], 1);
}

// Block-wide inclusive scan (Hillis-Steele): block-exclusive offsets + block sums.
__global__ __launch_bounds__(SCAN_BS) void scan1_kernel() {
    __shared__ int s[SCAN_BS];
    int i = blockIdx.x * SCAN_BS + threadIdx.x;
    int v = (i < NN) ? g_counts[i] : 0;
    s[threadIdx.x] = v;
    __syncthreads();
#pragma unroll
    for (int off = 1; off < SCAN_BS; off <<= 1) {
        int y = (threadIdx.x >= off) ? s[threadIdx.x - off] : 0;
        __syncthreads();
        s[threadIdx.x] += y;
        __syncthreads();
    }
    if (i < NN) g_offsets[i] = s[threadIdx.x] - v;   // exclusive within block
    if (threadIdx.x == SCAN_BS - 1) g_bsum[blockIdx.x] = s[SCAN_BS - 1];
}

// Exclusive scan of the 49 block sums: one warp, shfl-scan. Lane l owns
// values l and l+32 (second mostly OOB). Two-tier: scan lo 32, scan hi 17
// with carry = total(lo).
__global__ void scan2_kernel() {
    int lane = threadIdx.x;
    int vlo = (lane < NBLK) ? g_bsum[lane] : 0;
    int vhi = (lane + 32 < NBLK) ? g_bsum[lane + 32] : 0;
    int slo = vlo, shi = vhi;
#pragma unroll
    for (int off = 1; off < 32; off <<= 1) {
        int ylo = __shfl_up_sync(0xffffffffu, slo, off);
        int yhi = __shfl_up_sync(0xffffffffu, shi, off);
        if (lane >= off) { slo += ylo; shi += yhi; }
    }
    int tot_lo = __shfl_sync(0xffffffffu, slo, 31);
    if (lane < NBLK) g_bsum[lane] = slo - vlo;                    // exclusive
    if (lane + 32 < NBLK) g_bsum[lane + 32] = tot_lo + shi - vhi;
}

__global__ __launch_bounds__(256) void scan3_kernel() {
    int i = blockIdx.x * blockDim.x + threadIdx.x;
    if (i < NN) {
        int o = g_offsets[i] + g_bsum[i >> 10];   // L1-broadcast read
        g_offsets[i] = o;
        g_cursor[i]  = o;
    }
}

__global__ __launch_bounds__(256) void fill_kernel(const int* __restrict__ ei32,
                                                   const float* __restrict__ ew) {
    int e = blockIdx.x * blockDim.x + threadIdx.x;
    if (e >= EE) return;
    bool is64 = detect_i64(ei32);
    int src, dst;
    load_edge(ei32, is64, e, src, dst);
    int pos = atomicAdd(&g_cursor[dst], 1);
    g_recs[pos] = make_int2(src, __float_as_int(ew[e]));
}

// ---------------------------------------------------------------------------
// Gather: one warp per destination node, no atomics.
// Half-warps process edges pairwise, unrolled x2 (4 edges in flight per warp)
// to raise MLP against L2 latency; lane j<16 owns float4 j of the row.
// ---------------------------------------------------------------------------
__global__ __launch_bounds__(256) void gather_kernel(const float4* __restrict__ Xv,
                                                     float4* __restrict__ agg) {
    int warp = (blockIdx.x * blockDim.x + threadIdx.x) >> 5;
    if (warp >= NN) return;
    int lane = threadIdx.x & 31;
    int half = lane >> 4;
    int j    = lane & 15;

    int start = g_offsets[warp];
    int cnt   = g_counts[warp];

    float4 acc = make_float4(0.f, 0.f, 0.f, 0.f);
    int i = half;
    for (; i + 2 < cnt; i += 4) {
        int2  rec0 = g_recs[start + i];
        int2  rec1 = g_recs[start + i + 2];
        float4 x0  = Xv[rec0.x * 16 + j];
        float4 x1  = Xv[rec1.x * 16 + j];
        float w0   = __int_as_float(rec0.y);
        float w1   = __int_as_float(rec1.y);
        acc.x += x0.x * w0;  acc.y += x0.y * w0;
        acc.z += x0.z * w0;  acc.w += x0.w * w0;
        acc.x += x1.x * w1;  acc.y += x1.y * w1;
        acc.z += x1.z * w1;  acc.w += x1.w * w1;
    }
    if (i < cnt) {
        int2  rec = g_recs[start + i];
        float w   = __int_as_float(rec.y);
        float4 x  = Xv[rec.x * 16 + j];
        acc.x += x.x * w;  acc.y += x.y * w;
        acc.z += x.z * w;  acc.w += x.w * w;
    }
    acc.x += __shfl_down_sync(0xffffffffu, acc.x, 16);
    acc.y += __shfl_down_sync(0xffffffffu, acc.y, 16);
    acc.z += __shfl_down_sync(0xffffffffu, acc.z, 16);
    acc.w += __shfl_down_sync(0xffffffffu, acc.w, 16);
    if (half == 0) agg[warp * 16 + j] = acc;
}

// ---------------------------------------------------------------------------
// Fused dual-GEMM + bias + sigmoid (round-2 scalar version — measured good).
//   out = sigmoid(A @ Wrel^T + R @ Wroot^T + bias)
// 128 threads, 64-row tile. Thread (cg = tid&7, rg = tid>>3) computes
// 8 cols {cg*8+i} x 4 rows {rg*4+t}. A/R read straight from gmem (8
// same-address lanes coalesce; no cross-warp reuse exists). Weights in smem
// with 8x8 slot transpose so per-instruction LDS addresses are contiguous
// 128B (conflict-free): slot = kq*64 + (c&7)*8 + (c>>3).
// ---------------------------------------------------------------------------
__global__ __launch_bounds__(128) void gemm_bias_sigmoid_kernel(
    const float* __restrict__ A,
    const float* __restrict__ R,
    const float* __restrict__ Wrel,   // [64,64] row-major [out][in]
    const float* __restrict__ Wroot,
    const float* __restrict__ b0, const float* __restrict__ b1,
    const float* __restrict__ b2, const float* __restrict__ b3,
    float* __restrict__ out)
{
    __shared__ float4 WrS[16 * 64];   // 16KB
    __shared__ float4 WoS[16 * 64];

    int tid = threadIdx.x;
    const float4* Wrel4  = (const float4*)Wrel;
    const float4* Wroot4 = (const float4*)Wroot;
    for (int idx = tid; idx < 1024; idx += 128) {
        int c = idx >> 4, kq = idx & 15;
        int slot = kq * 64 + (c & 7) * 8 + (c >> 3);
        WrS[slot] = Wrel4[idx];
        WoS[slot] = Wroot4[idx];
    }
    __syncthreads();

    int cg = tid & 7;
    int rg = tid >> 3;
    int row0 = blockIdx.x * 64 + rg * 4;

    float acc[8][4];
#pragma unroll
    for (int i = 0; i < 8; i++)
#pragma unroll
        for (int t = 0; t < 4; t++) acc[i][t] = 0.f;

    const float4* A4 = (const float4*)A;
    const float4* R4 = (const float4*)R;
    bool full = (row0 + 3 < NN);

#pragma unroll 2
    for (int kq = 0; kq < 16; kq++) {
        float4 a[4], r[4];
#pragma unroll
        for (int t = 0; t < 4; t++) {
            int row = row0 + t;
            if (full || row < NN) {
                a[t] = A4[row * 16 + kq];
                r[t] = R4[row * 16 + kq];
            } else {
                a[t] = make_float4(0.f, 0.f, 0.f, 0.f);
                r[t] = make_float4(0.f, 0.f, 0.f, 0.f);
            }
        }
#pragma unroll
        for (int i = 0; i < 8; i++) {
            float4 wr = WrS[kq * 64 + i * 8 + cg];   // lanes cg=0..7 contiguous
            float4 wo = WoS[kq * 64 + i * 8 + cg];
#pragma unroll
            for (int t = 0; t < 4; t++) {
                acc[i][t] += a[t].x * wr.x + a[t].y * wr.y
                           + a[t].z * wr.z + a[t].w * wr.w
                           + r[t].x * wo.x + r[t].y * wo.y
                           + r[t].z * wo.z + r[t].w * wo.w;
            }
        }
    }

    float bias[8];
#pragma unroll
    for (int i = 0; i < 8; i++) {
        int c = cg * 8 + i;
        bias[i] = b0[c] + b1[c];
        if (b2 != nullptr) bias[i] += b2[c] + b3[c];
    }

#pragma unroll
    for (int t = 0; t < 4; t++) {
        int row = row0 + t;
        if (row < NN) {
            float4 o0, o1;
            o0.x = 1.f / (1.f + __expf(-(acc[0][t] + bias[0])));
            o0.y = 1.f / (1.f + __expf(-(acc[1][t] + bias[1])));
            o0.z = 1.f / (1.f + __expf(-(acc[2][t] + bias[2])));
            o0.w = 1.f / (1.f + __expf(-(acc[3][t] + bias[3])));
            o1.x = 1.f / (1.f + __expf(-(acc[4][t] + bias[4])));
            o1.y = 1.f / (1.f + __expf(-(acc[5][t] + bias[5])));
            o1.z = 1.f / (1.f + __expf(-(acc[6][t] + bias[6])));
            o1.w = 1.f / (1.f + __expf(-(acc[7][t] + bias[7])));
            float4* op = (float4*)&out[row * DD + cg * 8];
            op[0] = o0;
            op[1] = o1;
        }
    }
}

// ---------------------------------------------------------------------------
extern "C" void kernel_launch(void* const* d_in, const int* in_sizes, int n_in,
                              void* d_out, int out_size)
{
    const float* X      = (const float*)d_in[0];
    const int*   ei     = (const int*)  d_in[1];   // raw; dtype auto-detected
    const float* ew     = (const float*)d_in[2];
    const float* Wrel1  = (const float*)d_in[3];
    const float* brel1  = (const float*)d_in[4];
    const float* Wroot1 = (const float*)d_in[5];
    const float* broot1 = (const float*)d_in[6];
    const float* brel2  = (const float*)d_in[8];
    const float* broot2 = (const float*)d_in[10];
    const float* Wrel3  = (const float*)d_in[11];
    const float* brel3  = (const float*)d_in[12];
    const float* Wroot3 = (const float*)d_in[13];
    const float* broot3 = (const float*)d_in[14];
    float* out = (float*)d_out;

    float *agg, *h;
    cudaGetSymbolAddress((void**)&agg, g_AGG);
    cudaGetSymbolAddress((void**)&h,   g_H);

    // --- CSR build (once; shared by both aggregation passes) ---
    zero_counts_kernel<<<(NN + 255) / 256, 256>>>();
    hist_kernel<<<(EE + 255) / 256, 256>>>(ei);
    scan1_kernel<<<NBLK, SCAN_BS>>>();
    scan2_kernel<<<1, 32>>>();
    scan3_kernel<<<(NN + 255) / 256, 256>>>();
    fill_kernel<<<(EE + 255) / 256, 256>>>(ei, ew);

    // --- pass 1: AGG = scatter(X[src]*w -> dst), atomic-free gather ---
    gather_kernel<<<(NN * 32 + 255) / 256, 256>>>((const float4*)X, (float4*)agg);

    // H = sigmoid(AGG@Wrel1^T + X@Wroot1^T + brel1+broot1+brel2+broot2)
    gemm_bias_sigmoid_kernel<<<(NN + 63) / 64, 128>>>(
        agg, X, Wrel1, Wroot1, brel1, broot1, brel2, broot2, h);

    // --- pass 2: AGG = scatter(H[src]*w -> dst) ---
    gather_kernel<<<(NN * 32 + 255) / 256, 256>>>((const float4*)h, (float4*)agg);

    // out = sigmoid(AGG@Wrel3^T + H@Wroot3^T + brel3+broot3)
    gemm_bias_sigmoid_kernel<<<(NN + 63) / 64, 128>>>(
        agg, h, Wrel3, Wroot3, brel3, broot3, nullptr, nullptr, out);
}